// round 12
// baseline (speedup 1.0000x reference)
#include <cuda_runtime.h>
#include <cuda_fp16.h>
#include <math.h>
#include <stdint.h>

#define SEQ    1024
#define DIM    1024
#define NH     16
#define HD     64
#define LAYERS 6
#define BATCH  2
#define ROWS   (BATCH*SEQ)   // 2048
#define FFD    (4*DIM)       // 4096
#define VOCAB  32000

// ---- scratch (device globals: allocation-free) ----
__device__ float    g_x   [ROWS*DIM];
__device__ __half   g_xh  [ROWS*DIM];
__device__ __half   g_qkvh[ROWS*3*DIM];
__device__ __half   g_aoh [ROWS*DIM];
__device__ __half   g_ffh [ROWS*FFD];
__device__ float    g_t   [ROWS*DIM];
__device__ float    g_rowsum[ROWS];
// fp16 weights, interleaved as half2(W[2k][n], W[2k+1][n]) stored per uint32
__device__ uint32_t g_qkvwh[(DIM/2)*3*DIM];
__device__ uint32_t g_outwh[(DIM/2)*DIM];
__device__ uint32_t g_ff1wh[(DIM/2)*FFD];
__device__ uint32_t g_ff2wh[(FFD/2)*DIM];
__device__ uint32_t g_headwh[(size_t)(DIM/2)*VOCAB];

__device__ __forceinline__ uint32_t packh2(float a, float b) {
    __half2 h = __floats2half2_rn(a, b);
    return *(uint32_t*)&h;
}

// =================== weight conversion (fp32 -> interleaved fp16) ===================
__global__ void convert_w(const float* __restrict__ W, uint32_t* __restrict__ Wh, int N) {
    int idx = blockIdx.x * 256 + threadIdx.x;   // over (K/2)*N
    int kk = idx / N, n = idx - kk * N;
    Wh[idx] = packh2(W[(size_t)(2*kk) * N + n], W[(size_t)(2*kk+1) * N + n]);
}

// =================== embedding (fp32 + fp16) ===================
__global__ void embed_kernel(const int* __restrict__ X, const float* __restrict__ tok,
                             const float* __restrict__ pos, float* __restrict__ x,
                             __half* __restrict__ xh) {
    int row = blockIdx.x;
    int s   = row % SEQ;
    int v   = X[row];
    const float* te = tok + (size_t)v * DIM;
    const float* pe = pos + (size_t)s * DIM;
    float*  xr  = x  + (size_t)row * DIM;
    __half* xhr = xh + (size_t)row * DIM;
    for (int d = threadIdx.x; d < DIM; d += blockDim.x) {
        float val = te[d] + pe[d];
        xr[d]  = val;
        xhr[d] = __float2half(val);
    }
}

// =================== fp16 tensor-core GEMM, 4-stage cp.async pipeline (R7-proven) ===================
// EPI 0: fp32 out. EPI 1: GELU -> fp16. EPI 2: bias-only -> fp16.
// EPI 3: exp(logit+bias) -> fp32 + atomic row sums (fused softmax numerator).
__device__ __forceinline__ float gelu_exact(float v) {
    return 0.5f * v * (1.0f + erff(v * 0.70710678118654752f));
}
__device__ __forceinline__ void cp16(uint32_t dst, const void* src) {
    asm volatile("cp.async.cg.shared.global [%0], [%1], 16;\n" :: "r"(dst), "l"(src));
}

template<int EPI, int MT>
__global__ __launch_bounds__(256, MT==2 ? 3 : 2) void gemm_tc(
    const __half* __restrict__ A, const uint32_t* __restrict__ Bh,
    const float* __restrict__ bias, void* __restrict__ Cv,
    float* __restrict__ rowsum, int N, int K) {
    constexpr int BM = MT * 32;
    __shared__ __align__(16) uint32_t As2[4][BM][12];
    __shared__ __align__(16) uint32_t Bs2[4][8][136];

    const int t    = threadIdx.x;
    const int warp = t >> 5, lane = t & 31;
    const int wm   = warp >> 2, wn = warp & 3;      // 2 x 4 warp grid
    const int g    = lane >> 2, tig = lane & 3;
    const int bm   = blockIdx.y * BM;
    const int bn   = blockIdx.x * 128;

    const int arow = t >> 1, achk = t & 1;
    const int brow = t >> 5, bcol = (t & 31) << 2;

    float acc[MT][4][4];
    #pragma unroll
    for (int i = 0; i < MT; i++)
        #pragma unroll
        for (int j = 0; j < 4; j++)
            #pragma unroll
            for (int r = 0; r < 4; r++) acc[i][j][r] = 0.f;

    const int nkt = K >> 4;

    #define ISSUE(kt_) do {                                                          \
        int stg_ = (kt_) & 3;                                                        \
        int k0_  = (kt_) << 4;                                                       \
        if (MT == 4 || t < 128) {                                                    \
            uint32_t d_ = (uint32_t)__cvta_generic_to_shared(&As2[stg_][arow][achk*4]); \
            cp16(d_, A + (size_t)(bm + arow) * K + k0_ + achk*8);                    \
        }                                                                            \
        uint32_t d2_ = (uint32_t)__cvta_generic_to_shared(&Bs2[stg_][brow][bcol]);   \
        cp16(d2_, Bh + (size_t)((k0_ >> 1) + brow) * N + bn + bcol);                 \
        asm volatile("cp.async.commit_group;\n");                                    \
    } while (0)

    ISSUE(0); ISSUE(1); ISSUE(2);

    for (int kt = 0; kt < nkt; kt++) {
        asm volatile("cp.async.wait_group 2;\n");
        __syncthreads();
        if (kt + 3 < nkt) ISSUE(kt + 3);
        else              asm volatile("cp.async.commit_group;\n");

        const int cur = kt & 3;
        uint32_t a[MT][4];
        #pragma unroll
        for (int mt = 0; mt < MT; mt++) {
            int m = wm * (MT * 16) + mt * 16 + g;
            a[mt][0] = As2[cur][m    ][tig];
            a[mt][1] = As2[cur][m + 8][tig];
            a[mt][2] = As2[cur][m    ][tig + 4];
            a[mt][3] = As2[cur][m + 8][tig + 4];
        }
        #pragma unroll
        for (int nt = 0; nt < 4; nt++) {
            int n = wn * 32 + nt * 8 + g;
            uint32_t b0 = Bs2[cur][tig    ][n];
            uint32_t b1 = Bs2[cur][tig + 4][n];
            #pragma unroll
            for (int mt = 0; mt < MT; mt++) {
                asm volatile(
                    "mma.sync.aligned.m16n8k16.row.col.f32.f16.f16.f32 "
                    "{%0,%1,%2,%3}, {%4,%5,%6,%7}, {%8,%9}, {%0,%1,%2,%3};\n"
                    : "+f"(acc[mt][nt][0]), "+f"(acc[mt][nt][1]),
                      "+f"(acc[mt][nt][2]), "+f"(acc[mt][nt][3])
                    : "r"(a[mt][0]), "r"(a[mt][1]), "r"(a[mt][2]), "r"(a[mt][3]),
                      "r"(b0), "r"(b1));
            }
        }
    }
    #undef ISSUE

    // epilogue: c0/c1 at (row g, cols 2tig,2tig+1), c2/c3 at row g+8
    float rs0[MT], rs1[MT];
    if (EPI == 3) {
        #pragma unroll
        for (int mt = 0; mt < MT; mt++) { rs0[mt] = 0.f; rs1[mt] = 0.f; }
    }
    #pragma unroll
    for (int nt = 0; nt < 4; nt++) {
        int n = bn + wn * 32 + nt * 8 + 2 * tig;
        float2 bv = *(const float2*)(bias + n);
        #pragma unroll
        for (int mt = 0; mt < MT; mt++) {
            int r = bm + wm * (MT * 16) + mt * 16 + g;
            float o00 = acc[mt][nt][0] + bv.x, o01 = acc[mt][nt][1] + bv.y;
            float o10 = acc[mt][nt][2] + bv.x, o11 = acc[mt][nt][3] + bv.y;
            if (EPI == 1) {
                o00 = gelu_exact(o00); o01 = gelu_exact(o01);
                o10 = gelu_exact(o10); o11 = gelu_exact(o11);
            }
            if (EPI == 3) {
                o00 = expf(o00); o01 = expf(o01);
                o10 = expf(o10); o11 = expf(o11);
                rs0[mt] += o00 + o01;
                rs1[mt] += o10 + o11;
            }
            if (EPI == 1 || EPI == 2) {
                __half* Ch = (__half*)Cv;
                *(__half2*)(Ch + (size_t)r * N + n)       = __floats2half2_rn(o00, o01);
                *(__half2*)(Ch + (size_t)(r + 8) * N + n) = __floats2half2_rn(o10, o11);
            } else {
                float* Cf = (float*)Cv;
                *(float2*)(Cf + (size_t)r * N + n)       = make_float2(o00, o01);
                *(float2*)(Cf + (size_t)(r + 8) * N + n) = make_float2(o10, o11);
            }
        }
    }
    if (EPI == 3) {
        #pragma unroll
        for (int mt = 0; mt < MT; mt++) {
            float s0 = rs0[mt], s1 = rs1[mt];
            s0 += __shfl_xor_sync(0xffffffffu, s0, 1);
            s0 += __shfl_xor_sync(0xffffffffu, s0, 2);
            s1 += __shfl_xor_sync(0xffffffffu, s1, 1);
            s1 += __shfl_xor_sync(0xffffffffu, s1, 2);
            if (tig == 0) {
                int r = bm + wm * (MT * 16) + mt * 16 + g;
                atomicAdd(&rowsum[r],     s0);
                atomicAdd(&rowsum[r + 8], s1);
            }
        }
    }
}

// =================== tensor-core flash attention: 128-row Q tiles, 256 threads ===================
// block = (qt, h, b); 8 warps, warp w owns q rows qt*128 + w*16 + [0,16).
__global__ __launch_bounds__(256) void attn_kernel(const __half* __restrict__ qkvh,
                                                   __half* __restrict__ out) {
    __shared__ __align__(16) __half   Qs[128][72];
    __shared__ __align__(16) __half   Ks[64][72];
    __shared__ __align__(16) uint32_t Vs2[32][68];

    const int qt = blockIdx.x, h = blockIdx.y, b = blockIdx.z;
    const int t  = threadIdx.x;
    const int w  = t >> 5, lane = t & 31;
    const int g  = lane >> 2, tig = lane & 3;
    const int RS = 3*DIM;
    const __half* base = qkvh + (size_t)(b*SEQ) * RS + h * (3*HD);

    // load Q tile (128x64 halves)
    #pragma unroll
    for (int i = 0; i < 4; i++) {
        int f = t + i*256;
        int r = f >> 3, c = (f & 7) << 3;
        *(uint4*)&Qs[r][c] = *(const uint4*)(base + (size_t)(qt*128 + r) * RS + c);
    }
    __syncthreads();

    uint32_t qf[4][4];
    {
        const __half* r0 = &Qs[w*16 + g    ][0];
        const __half* r8 = &Qs[w*16 + g + 8][0];
        #pragma unroll
        for (int kc = 0; kc < 4; kc++) {
            qf[kc][0] = *(const uint32_t*)(r0 + kc*16 + 2*tig);
            qf[kc][1] = *(const uint32_t*)(r8 + kc*16 + 2*tig);
            qf[kc][2] = *(const uint32_t*)(r0 + kc*16 + 8 + 2*tig);
            qf[kc][3] = *(const uint32_t*)(r8 + kc*16 + 8 + 2*tig);
        }
    }

    float m0 = -INFINITY, m1 = -INFINITY, l0 = 0.f, l1 = 0.f;
    float o[8][4];
    #pragma unroll
    for (int i = 0; i < 8; i++)
        #pragma unroll
        for (int j = 0; j < 4; j++) o[i][j] = 0.f;

    const int q0 = qt*128 + w*16 + g;
    const int q1 = q0 + 8;
    const int nkt = 2*qt + 2;   // K tiles covering rows <= qt*128+127

    for (int kt = 0; kt < nkt; kt++) {
        __syncthreads();
        // load K tile (64x64)
        #pragma unroll
        for (int i = 0; i < 2; i++) {
            int f = t + i*256;
            int r = f >> 3, c = (f & 7) << 3;
            *(uint4*)&Ks[r][c] = *(const uint4*)(base + (size_t)(kt*64 + r) * RS + 64 + c);
        }
        // load V tile (64x64), interleaved over s-pairs
        {
            int rp = t >> 3, c = (t & 7) << 3;
            const __half* v0 = base + (size_t)(kt*64 + 2*rp) * RS + 128 + c;
            uint4 lo = *(const uint4*)v0;
            uint4 hi = *(const uint4*)(v0 + RS);
            const ushort* ls = (const ushort*)&lo;
            const ushort* hs = (const ushort*)&hi;
            uint32_t pk[8];
            #pragma unroll
            for (int j = 0; j < 8; j++) pk[j] = (uint32_t)ls[j] | ((uint32_t)hs[j] << 16);
            *(uint4*)&Vs2[rp][c]     = make_uint4(pk[0], pk[1], pk[2], pk[3]);
            *(uint4*)&Vs2[rp][c + 4] = make_uint4(pk[4], pk[5], pk[6], pk[7]);
        }
        __syncthreads();

        float s[8][4];
        #pragma unroll
        for (int i = 0; i < 8; i++)
            #pragma unroll
            for (int j = 0; j < 4; j++) s[i][j] = 0.f;
        #pragma unroll
        for (int kc = 0; kc < 4; kc++) {
            #pragma unroll
            for (int nt = 0; nt < 8; nt++) {
                uint32_t b0 = *(const uint32_t*)(&Ks[nt*8 + g][kc*16 + 2*tig]);
                uint32_t b1 = *(const uint32_t*)(&Ks[nt*8 + g][kc*16 + 8 + 2*tig]);
                asm volatile(
                    "mma.sync.aligned.m16n8k16.row.col.f32.f16.f16.f32 "
                    "{%0,%1,%2,%3}, {%4,%5,%6,%7}, {%8,%9}, {%0,%1,%2,%3};\n"
                    : "+f"(s[nt][0]), "+f"(s[nt][1]), "+f"(s[nt][2]), "+f"(s[nt][3])
                    : "r"(qf[kc][0]), "r"(qf[kc][1]), "r"(qf[kc][2]), "r"(qf[kc][3]),
                      "r"(b0), "r"(b1));
            }
        }

        float tm0 = -INFINITY, tm1 = -INFINITY;
        #pragma unroll
        for (int nt = 0; nt < 8; nt++) {
            int c0 = kt*64 + nt*8 + 2*tig, c1 = c0 + 1;
            s[nt][0] = (c0 <= q0) ? s[nt][0] * 0.125f : -INFINITY;
            s[nt][1] = (c1 <= q0) ? s[nt][1] * 0.125f : -INFINITY;
            s[nt][2] = (c0 <= q1) ? s[nt][2] * 0.125f : -INFINITY;
            s[nt][3] = (c1 <= q1) ? s[nt][3] * 0.125f : -INFINITY;
            tm0 = fmaxf(tm0, fmaxf(s[nt][0], s[nt][1]));
            tm1 = fmaxf(tm1, fmaxf(s[nt][2], s[nt][3]));
        }
        tm0 = fmaxf(tm0, __shfl_xor_sync(0xffffffffu, tm0, 1));
        tm0 = fmaxf(tm0, __shfl_xor_sync(0xffffffffu, tm0, 2));
        tm1 = fmaxf(tm1, __shfl_xor_sync(0xffffffffu, tm1, 1));
        tm1 = fmaxf(tm1, __shfl_xor_sync(0xffffffffu, tm1, 2));

        float nm0 = fmaxf(m0, tm0), nm1 = fmaxf(m1, tm1);
        float corr0 = expf(m0 - nm0), corr1 = expf(m1 - nm1);
        m0 = nm0; m1 = nm1;

        uint32_t pf[4][4];
        float ls0 = 0.f, ls1 = 0.f;
        #pragma unroll
        for (int j = 0; j < 4; j++) {
            float p00 = expf(s[2*j][0]   - m0), p01 = expf(s[2*j][1]   - m0);
            float p02 = expf(s[2*j][2]   - m1), p03 = expf(s[2*j][3]   - m1);
            float p10 = expf(s[2*j+1][0] - m0), p11 = expf(s[2*j+1][1] - m0);
            float p12 = expf(s[2*j+1][2] - m1), p13 = expf(s[2*j+1][3] - m1);
            ls0 += p00 + p01 + p10 + p11;
            ls1 += p02 + p03 + p12 + p13;
            pf[j][0] = packh2(p00, p01);
            pf[j][1] = packh2(p02, p03);
            pf[j][2] = packh2(p10, p11);
            pf[j][3] = packh2(p12, p13);
        }
        ls0 += __shfl_xor_sync(0xffffffffu, ls0, 1);
        ls0 += __shfl_xor_sync(0xffffffffu, ls0, 2);
        ls1 += __shfl_xor_sync(0xffffffffu, ls1, 1);
        ls1 += __shfl_xor_sync(0xffffffffu, ls1, 2);
        l0 = l0 * corr0 + ls0;
        l1 = l1 * corr1 + ls1;

        #pragma unroll
        for (int nt = 0; nt < 8; nt++) {
            o[nt][0] *= corr0; o[nt][1] *= corr0;
            o[nt][2] *= corr1; o[nt][3] *= corr1;
        }

        #pragma unroll
        for (int j = 0; j < 4; j++) {
            #pragma unroll
            for (int nt = 0; nt < 8; nt++) {
                uint32_t b0 = Vs2[8*j + tig    ][nt*8 + g];
                uint32_t b1 = Vs2[8*j + tig + 4][nt*8 + g];
                asm volatile(
                    "mma.sync.aligned.m16n8k16.row.col.f32.f16.f16.f32 "
                    "{%0,%1,%2,%3}, {%4,%5,%6,%7}, {%8,%9}, {%0,%1,%2,%3};\n"
                    : "+f"(o[nt][0]), "+f"(o[nt][1]), "+f"(o[nt][2]), "+f"(o[nt][3])
                    : "r"(pf[j][0]), "r"(pf[j][1]), "r"(pf[j][2]), "r"(pf[j][3]),
                      "r"(b0), "r"(b1));
            }
        }
    }

    float inv0 = 1.f / l0, inv1 = 1.f / l1;
    __half* or0 = out + (size_t)(b*SEQ + q0) * DIM + h * HD;
    __half* or1 = out + (size_t)(b*SEQ + q1) * DIM + h * HD;
    #pragma unroll
    for (int nt = 0; nt < 8; nt++) {
        int c = nt*8 + 2*tig;
        *(__half2*)(or0 + c) = __floats2half2_rn(o[nt][0] * inv0, o[nt][1] * inv0);
        *(__half2*)(or1 + c) = __floats2half2_rn(o[nt][2] * inv1, o[nt][3] * inv1);
    }
}

// =================== residual add + LayerNorm (fp32 + fp16 out) ===================
__global__ __launch_bounds__(256) void add_ln_kernel(
    const float* __restrict__ x, const float* __restrict__ a,
    const float* __restrict__ scale, const float* __restrict__ bias,
    float* __restrict__ out, __half* __restrict__ outh, int has_a) {
    int row = blockIdx.x;
    const float* xr = x + (size_t)row * DIM;
    const float* ar = a + (size_t)row * DIM;
    int t = threadIdx.x;
    float v[4];
    float s = 0.f, s2 = 0.f;
    #pragma unroll
    for (int i = 0; i < 4; i++) {
        int d = t + i*256;
        float val = xr[d] + (has_a ? ar[d] : 0.f);
        v[i] = val; s += val; s2 += val*val;
    }
    __shared__ float red[2][8];
    #pragma unroll
    for (int off = 16; off; off >>= 1) {
        s  += __shfl_xor_sync(0xffffffffu, s,  off);
        s2 += __shfl_xor_sync(0xffffffffu, s2, off);
    }
    if ((t & 31) == 0) { red[0][t>>5] = s; red[1][t>>5] = s2; }
    __syncthreads();
    float ts = 0.f, ts2 = 0.f;
    #pragma unroll
    for (int i = 0; i < 8; i++) { ts += red[0][i]; ts2 += red[1][i]; }
    float mean = ts * (1.0f/DIM);
    float var  = ts2 * (1.0f/DIM) - mean*mean;
    float inv  = rsqrtf(var + 1e-5f);
    float*  orow  = out  + (size_t)row * DIM;
    __half* orowh = outh + (size_t)row * DIM;
    #pragma unroll
    for (int i = 0; i < 4; i++) {
        int d = t + i*256;
        float val = (v[i] - mean) * inv * scale[d] + bias[d];
        orow[d]  = val;
        orowh[d] = __float2half(val);
    }
}

// =================== fused-softmax helpers ===================
__global__ void zero_rowsum_kernel(float* __restrict__ rowsum) {
    rowsum[blockIdx.x * 256 + threadIdx.x] = 0.f;
}
__global__ __launch_bounds__(256) void normalize_kernel(float* __restrict__ out,
                                                        const float* __restrict__ rowsum) {
    int row = blockIdx.x;
    float inv = 1.f / rowsum[row];
    float4* r = (float4*)(out + (size_t)row * VOCAB);
    for (int i = threadIdx.x; i < VOCAB/4; i += 256) {
        float4 v = r[i];
        v.x *= inv; v.y *= inv; v.z *= inv; v.w *= inv;
        r[i] = v;
    }
}

// =================== launch ===================
extern "C" void kernel_launch(void* const* d_in, const int* in_sizes, int n_in,
                              void* d_out, int out_size) {
    const int*   X      = (const int*)  d_in[0];
    const float* tok    = (const float*)d_in[1];
    const float* pos    = (const float*)d_in[2];
    const float* qkv_w  = (const float*)d_in[3];
    const float* qkv_b  = (const float*)d_in[4];
    const float* out_w  = (const float*)d_in[5];
    const float* out_b  = (const float*)d_in[6];
    const float* ln1_s  = (const float*)d_in[7];
    const float* ln1_b  = (const float*)d_in[8];
    const float* ln2_s  = (const float*)d_in[9];
    const float* ln2_b  = (const float*)d_in[10];
    const float* ff1_w  = (const float*)d_in[11];
    const float* ff1_b  = (const float*)d_in[12];
    const float* ff2_w  = (const float*)d_in[13];
    const float* ff2_b  = (const float*)d_in[14];
    const float* lnf_s  = (const float*)d_in[15];
    const float* lnf_b  = (const float*)d_in[16];
    const float* head_w = (const float*)d_in[17];
    const float* head_b = (const float*)d_in[18];
    float* outp = (float*)d_out;

    float *x, *tmp, *rowsum;
    __half *xh, *qkvh, *aoh, *ffh;
    uint32_t *qkvwh, *outwh, *ff1wh, *ff2wh, *headwh;
    cudaGetSymbolAddress((void**)&x,      g_x);
    cudaGetSymbolAddress((void**)&xh,     g_xh);
    cudaGetSymbolAddress((void**)&qkvh,   g_qkvh);
    cudaGetSymbolAddress((void**)&aoh,    g_aoh);
    cudaGetSymbolAddress((void**)&ffh,    g_ffh);
    cudaGetSymbolAddress((void**)&tmp,    g_t);
    cudaGetSymbolAddress((void**)&rowsum, g_rowsum);
    cudaGetSymbolAddress((void**)&qkvwh,  g_qkvwh);
    cudaGetSymbolAddress((void**)&outwh,  g_outwh);
    cudaGetSymbolAddress((void**)&ff1wh,  g_ff1wh);
    cudaGetSymbolAddress((void**)&ff2wh,  g_ff2wh);
    cudaGetSymbolAddress((void**)&headwh, g_headwh);

    // one-time weight conversions (per launch)
    convert_w<<<(DIM/2)*3*DIM/256, 256>>>(qkv_w,  qkvwh,  3*DIM);
    convert_w<<<(DIM/2)*DIM/256,   256>>>(out_w,  outwh,  DIM);
    convert_w<<<(DIM/2)*FFD/256,   256>>>(ff1_w,  ff1wh,  FFD);
    convert_w<<<(FFD/2)*DIM/256,   256>>>(ff2_w,  ff2wh,  DIM);
    convert_w<<<(DIM/2)*VOCAB/256, 256>>>(head_w, headwh, VOCAB);

    embed_kernel<<<ROWS, 256>>>(X, tok, pos, x, xh);

    for (int l = 0; l < LAYERS; l++) {
        gemm_tc<2,4><<<dim3(3*DIM/128, ROWS/128), 256>>>(xh, qkvwh, qkv_b, qkvh, nullptr, 3*DIM, DIM);
        attn_kernel<<<dim3(SEQ/128, NH, BATCH), 256>>>(qkvh, aoh);
        gemm_tc<0,2><<<dim3(DIM/128, ROWS/64), 256>>>(aoh, outwh, out_b, tmp, nullptr, DIM, DIM);
        add_ln_kernel<<<ROWS, 256>>>(x, tmp, ln1_s, ln1_b, x, xh, 1);
        gemm_tc<1,4><<<dim3(FFD/128, ROWS/128), 256>>>(xh, ff1wh, ff1_b, ffh, nullptr, FFD, DIM);
        gemm_tc<0,2><<<dim3(DIM/128, ROWS/64), 256>>>(ffh, ff2wh, ff2_b, tmp, nullptr, DIM, FFD);
        add_ln_kernel<<<ROWS, 256>>>(x, tmp, ln2_s, ln2_b, x, xh, 1);
    }
    add_ln_kernel<<<ROWS, 256>>>(x, x, lnf_s, lnf_b, x, xh, 0);
    zero_rowsum_kernel<<<ROWS/256, 256>>>(rowsum);
    gemm_tc<3,4><<<dim3(VOCAB/128, ROWS/128), 256>>>(xh, headwh, head_b, outp, rowsum, VOCAB, DIM);
    normalize_kernel<<<ROWS, 256>>>(outp, rowsum);
}

// round 14
// speedup vs baseline: 1.0206x; 1.0206x over previous
#include <cuda_runtime.h>
#include <cuda_fp16.h>
#include <math.h>
#include <stdint.h>

#define SEQ    1024
#define DIM    1024
#define NH     16
#define HD     64
#define LAYERS 6
#define BATCH  2
#define ROWS   (BATCH*SEQ)   // 2048
#define FFD    (4*DIM)       // 4096
#define VOCAB  32000

// ---- scratch (device globals: allocation-free) ----
__device__ float    g_x   [ROWS*DIM];
__device__ __half   g_xh  [ROWS*DIM];
__device__ __half   g_qkvh[ROWS*3*DIM];
__device__ __half   g_aoh [ROWS*DIM];
__device__ __half   g_ffh [ROWS*FFD];
__device__ float    g_t   [ROWS*DIM];
__device__ float    g_rowsum[ROWS];
// fp16 weights, interleaved as half2(W[2k][n], W[2k+1][n]) stored per uint32
__device__ uint32_t g_qkvwh[(DIM/2)*3*DIM];
__device__ uint32_t g_outwh[(DIM/2)*DIM];
__device__ uint32_t g_ff1wh[(DIM/2)*FFD];
__device__ uint32_t g_ff2wh[(FFD/2)*DIM];
__device__ uint32_t g_headwh[(size_t)(DIM/2)*VOCAB];

__device__ __forceinline__ uint32_t packh2(float a, float b) {
    __half2 h = __floats2half2_rn(a, b);
    return *(uint32_t*)&h;
}

// =================== weight conversion (fp32 -> interleaved fp16, vectorized) ===================
// One thread: reads float4 from rows 2kk and 2kk+1, writes uint4 (4 interleaved half2).
__global__ void convert_w(const float* __restrict__ W, uint32_t* __restrict__ Wh, int N) {
    int idx = blockIdx.x * 256 + threadIdx.x;   // over (K/2)*(N/4)
    int n4  = N >> 2;
    int kk  = idx / n4, n = (idx - kk * n4) << 2;
    float4 a = *(const float4*)(W + (size_t)(2*kk)   * N + n);
    float4 b = *(const float4*)(W + (size_t)(2*kk+1) * N + n);
    uint4 o;
    o.x = packh2(a.x, b.x); o.y = packh2(a.y, b.y);
    o.z = packh2(a.z, b.z); o.w = packh2(a.w, b.w);
    *(uint4*)(Wh + (size_t)kk * N + n) = o;
}

// =================== embedding (fp32 + fp16) ===================
__global__ void embed_kernel(const int* __restrict__ X, const float* __restrict__ tok,
                             const float* __restrict__ pos, float* __restrict__ x,
                             __half* __restrict__ xh) {
    int row = blockIdx.x;
    int s   = row % SEQ;
    int v   = X[row];
    const float* te = tok + (size_t)v * DIM;
    const float* pe = pos + (size_t)s * DIM;
    float*  xr  = x  + (size_t)row * DIM;
    __half* xhr = xh + (size_t)row * DIM;
    for (int d = threadIdx.x; d < DIM; d += blockDim.x) {
        float val = te[d] + pe[d];
        xr[d]  = val;
        xhr[d] = __float2half(val);
    }
}

// =================== fp16 tensor-core GEMM, 4-stage cp.async pipeline (R7-proven) ===================
// EPI 0: fp32 out. EPI 1: GELU -> fp16. EPI 2: bias-only -> fp16.
// EPI 3: exp(logit+bias) -> fp32 + atomic row sums (fused softmax numerator).
__device__ __forceinline__ float gelu_exact(float v) {
    return 0.5f * v * (1.0f + erff(v * 0.70710678118654752f));
}
__device__ __forceinline__ void cp16(uint32_t dst, const void* src) {
    asm volatile("cp.async.cg.shared.global [%0], [%1], 16;\n" :: "r"(dst), "l"(src));
}

template<int EPI, int MT>
__global__ __launch_bounds__(256, MT==2 ? 3 : 2) void gemm_tc(
    const __half* __restrict__ A, const uint32_t* __restrict__ Bh,
    const float* __restrict__ bias, void* __restrict__ Cv,
    float* __restrict__ rowsum, int N, int K) {
    constexpr int BM = MT * 32;
    __shared__ __align__(16) uint32_t As2[4][BM][12];
    __shared__ __align__(16) uint32_t Bs2[4][8][136];

    const int t    = threadIdx.x;
    const int warp = t >> 5, lane = t & 31;
    const int wm   = warp >> 2, wn = warp & 3;      // 2 x 4 warp grid
    const int g    = lane >> 2, tig = lane & 3;
    const int bm   = blockIdx.y * BM;
    const int bn   = blockIdx.x * 128;

    const int arow = t >> 1, achk = t & 1;
    const int brow = t >> 5, bcol = (t & 31) << 2;

    float acc[MT][4][4];
    #pragma unroll
    for (int i = 0; i < MT; i++)
        #pragma unroll
        for (int j = 0; j < 4; j++)
            #pragma unroll
            for (int r = 0; r < 4; r++) acc[i][j][r] = 0.f;

    const int nkt = K >> 4;

    #define ISSUE(kt_) do {                                                          \
        int stg_ = (kt_) & 3;                                                        \
        int k0_  = (kt_) << 4;                                                       \
        if (MT == 4 || t < 128) {                                                    \
            uint32_t d_ = (uint32_t)__cvta_generic_to_shared(&As2[stg_][arow][achk*4]); \
            cp16(d_, A + (size_t)(bm + arow) * K + k0_ + achk*8);                    \
        }                                                                            \
        uint32_t d2_ = (uint32_t)__cvta_generic_to_shared(&Bs2[stg_][brow][bcol]);   \
        cp16(d2_, Bh + (size_t)((k0_ >> 1) + brow) * N + bn + bcol);                 \
        asm volatile("cp.async.commit_group;\n");                                    \
    } while (0)

    ISSUE(0); ISSUE(1); ISSUE(2);

    for (int kt = 0; kt < nkt; kt++) {
        asm volatile("cp.async.wait_group 2;\n");
        __syncthreads();
        if (kt + 3 < nkt) ISSUE(kt + 3);
        else              asm volatile("cp.async.commit_group;\n");

        const int cur = kt & 3;
        uint32_t a[MT][4];
        #pragma unroll
        for (int mt = 0; mt < MT; mt++) {
            int m = wm * (MT * 16) + mt * 16 + g;
            a[mt][0] = As2[cur][m    ][tig];
            a[mt][1] = As2[cur][m + 8][tig];
            a[mt][2] = As2[cur][m    ][tig + 4];
            a[mt][3] = As2[cur][m + 8][tig + 4];
        }
        #pragma unroll
        for (int nt = 0; nt < 4; nt++) {
            int n = wn * 32 + nt * 8 + g;
            uint32_t b0 = Bs2[cur][tig    ][n];
            uint32_t b1 = Bs2[cur][tig + 4][n];
            #pragma unroll
            for (int mt = 0; mt < MT; mt++) {
                asm volatile(
                    "mma.sync.aligned.m16n8k16.row.col.f32.f16.f16.f32 "
                    "{%0,%1,%2,%3}, {%4,%5,%6,%7}, {%8,%9}, {%0,%1,%2,%3};\n"
                    : "+f"(acc[mt][nt][0]), "+f"(acc[mt][nt][1]),
                      "+f"(acc[mt][nt][2]), "+f"(acc[mt][nt][3])
                    : "r"(a[mt][0]), "r"(a[mt][1]), "r"(a[mt][2]), "r"(a[mt][3]),
                      "r"(b0), "r"(b1));
            }
        }
    }
    #undef ISSUE

    // epilogue: c0/c1 at (row g, cols 2tig,2tig+1), c2/c3 at row g+8
    float rs0[MT], rs1[MT];
    if (EPI == 3) {
        #pragma unroll
        for (int mt = 0; mt < MT; mt++) { rs0[mt] = 0.f; rs1[mt] = 0.f; }
    }
    #pragma unroll
    for (int nt = 0; nt < 4; nt++) {
        int n = bn + wn * 32 + nt * 8 + 2 * tig;
        float2 bv = *(const float2*)(bias + n);
        #pragma unroll
        for (int mt = 0; mt < MT; mt++) {
            int r = bm + wm * (MT * 16) + mt * 16 + g;
            float o00 = acc[mt][nt][0] + bv.x, o01 = acc[mt][nt][1] + bv.y;
            float o10 = acc[mt][nt][2] + bv.x, o11 = acc[mt][nt][3] + bv.y;
            if (EPI == 1) {
                o00 = gelu_exact(o00); o01 = gelu_exact(o01);
                o10 = gelu_exact(o10); o11 = gelu_exact(o11);
            }
            if (EPI == 3) {
                o00 = expf(o00); o01 = expf(o01);
                o10 = expf(o10); o11 = expf(o11);
                rs0[mt] += o00 + o01;
                rs1[mt] += o10 + o11;
            }
            if (EPI == 1 || EPI == 2) {
                __half* Ch = (__half*)Cv;
                *(__half2*)(Ch + (size_t)r * N + n)       = __floats2half2_rn(o00, o01);
                *(__half2*)(Ch + (size_t)(r + 8) * N + n) = __floats2half2_rn(o10, o11);
            } else {
                float* Cf = (float*)Cv;
                *(float2*)(Cf + (size_t)r * N + n)       = make_float2(o00, o01);
                *(float2*)(Cf + (size_t)(r + 8) * N + n) = make_float2(o10, o11);
            }
        }
    }
    if (EPI == 3) {
        #pragma unroll
        for (int mt = 0; mt < MT; mt++) {
            float s0 = rs0[mt], s1 = rs1[mt];
            s0 += __shfl_xor_sync(0xffffffffu, s0, 1);
            s0 += __shfl_xor_sync(0xffffffffu, s0, 2);
            s1 += __shfl_xor_sync(0xffffffffu, s1, 1);
            s1 += __shfl_xor_sync(0xffffffffu, s1, 2);
            if (tig == 0) {
                int r = bm + wm * (MT * 16) + mt * 16 + g;
                atomicAdd(&rowsum[r],     s0);
                atomicAdd(&rowsum[r + 8], s1);
            }
        }
    }
}

// =================== tensor-core flash attention (fp16 mma, fp32 softmax/acc) ===================
__global__ __launch_bounds__(128) void attn_kernel(const __half* __restrict__ qkvh,
                                                   __half* __restrict__ out) {
    __shared__ __align__(16) __half   Qs[64][72];
    __shared__ __align__(16) __half   Ks[64][72];
    __shared__ __align__(16) uint32_t Vs2[32][68];

    const int qt = blockIdx.x, h = blockIdx.y, b = blockIdx.z;
    const int t  = threadIdx.x;
    const int w  = t >> 5, lane = t & 31;
    const int g  = lane >> 2, tig = lane & 3;
    const int RS = 3*DIM;
    const __half* base = qkvh + (size_t)(b*SEQ) * RS + h * (3*HD);

    #pragma unroll
    for (int i = 0; i < 4; i++) {
        int f = t + i*128;
        int r = f >> 3, c = (f & 7) << 3;
        *(uint4*)&Qs[r][c] = *(const uint4*)(base + (size_t)(qt*64 + r) * RS + c);
    }
    __syncthreads();

    uint32_t qf[4][4];
    {
        const __half* r0 = &Qs[w*16 + g    ][0];
        const __half* r8 = &Qs[w*16 + g + 8][0];
        #pragma unroll
        for (int kc = 0; kc < 4; kc++) {
            qf[kc][0] = *(const uint32_t*)(r0 + kc*16 + 2*tig);
            qf[kc][1] = *(const uint32_t*)(r8 + kc*16 + 2*tig);
            qf[kc][2] = *(const uint32_t*)(r0 + kc*16 + 8 + 2*tig);
            qf[kc][3] = *(const uint32_t*)(r8 + kc*16 + 8 + 2*tig);
        }
    }

    float m0 = -INFINITY, m1 = -INFINITY, l0 = 0.f, l1 = 0.f;
    float o[8][4];
    #pragma unroll
    for (int i = 0; i < 8; i++)
        #pragma unroll
        for (int j = 0; j < 4; j++) o[i][j] = 0.f;

    const int q0 = qt*64 + w*16 + g;
    const int q1 = q0 + 8;

    for (int kt = 0; kt <= qt; kt++) {
        __syncthreads();
        #pragma unroll
        for (int i = 0; i < 4; i++) {
            int f = t + i*128;
            int r = f >> 3, c = (f & 7) << 3;
            *(uint4*)&Ks[r][c] = *(const uint4*)(base + (size_t)(kt*64 + r) * RS + 64 + c);
        }
        #pragma unroll
        for (int i = 0; i < 2; i++) {
            int f = t + i*128;
            int rp = f >> 3, c = (f & 7) << 3;
            const __half* v0 = base + (size_t)(kt*64 + 2*rp) * RS + 128 + c;
            uint4 lo = *(const uint4*)v0;
            uint4 hi = *(const uint4*)(v0 + RS);
            const ushort* ls = (const ushort*)&lo;
            const ushort* hs = (const ushort*)&hi;
            uint32_t pk[8];
            #pragma unroll
            for (int j = 0; j < 8; j++) pk[j] = (uint32_t)ls[j] | ((uint32_t)hs[j] << 16);
            *(uint4*)&Vs2[rp][c]     = make_uint4(pk[0], pk[1], pk[2], pk[3]);
            *(uint4*)&Vs2[rp][c + 4] = make_uint4(pk[4], pk[5], pk[6], pk[7]);
        }
        __syncthreads();

        float s[8][4];
        #pragma unroll
        for (int i = 0; i < 8; i++)
            #pragma unroll
            for (int j = 0; j < 4; j++) s[i][j] = 0.f;
        #pragma unroll
        for (int kc = 0; kc < 4; kc++) {
            #pragma unroll
            for (int nt = 0; nt < 8; nt++) {
                uint32_t b0 = *(const uint32_t*)(&Ks[nt*8 + g][kc*16 + 2*tig]);
                uint32_t b1 = *(const uint32_t*)(&Ks[nt*8 + g][kc*16 + 8 + 2*tig]);
                asm volatile(
                    "mma.sync.aligned.m16n8k16.row.col.f32.f16.f16.f32 "
                    "{%0,%1,%2,%3}, {%4,%5,%6,%7}, {%8,%9}, {%0,%1,%2,%3};\n"
                    : "+f"(s[nt][0]), "+f"(s[nt][1]), "+f"(s[nt][2]), "+f"(s[nt][3])
                    : "r"(qf[kc][0]), "r"(qf[kc][1]), "r"(qf[kc][2]), "r"(qf[kc][3]),
                      "r"(b0), "r"(b1));
            }
        }

        float tm0 = -INFINITY, tm1 = -INFINITY;
        #pragma unroll
        for (int nt = 0; nt < 8; nt++) {
            int c0 = kt*64 + nt*8 + 2*tig, c1 = c0 + 1;
            s[nt][0] = (c0 <= q0) ? s[nt][0] * 0.125f : -INFINITY;
            s[nt][1] = (c1 <= q0) ? s[nt][1] * 0.125f : -INFINITY;
            s[nt][2] = (c0 <= q1) ? s[nt][2] * 0.125f : -INFINITY;
            s[nt][3] = (c1 <= q1) ? s[nt][3] * 0.125f : -INFINITY;
            tm0 = fmaxf(tm0, fmaxf(s[nt][0], s[nt][1]));
            tm1 = fmaxf(tm1, fmaxf(s[nt][2], s[nt][3]));
        }
        tm0 = fmaxf(tm0, __shfl_xor_sync(0xffffffffu, tm0, 1));
        tm0 = fmaxf(tm0, __shfl_xor_sync(0xffffffffu, tm0, 2));
        tm1 = fmaxf(tm1, __shfl_xor_sync(0xffffffffu, tm1, 1));
        tm1 = fmaxf(tm1, __shfl_xor_sync(0xffffffffu, tm1, 2));

        float nm0 = fmaxf(m0, tm0), nm1 = fmaxf(m1, tm1);
        float corr0 = expf(m0 - nm0), corr1 = expf(m1 - nm1);
        m0 = nm0; m1 = nm1;

        uint32_t pf[4][4];
        float ls0 = 0.f, ls1 = 0.f;
        #pragma unroll
        for (int j = 0; j < 4; j++) {
            float p00 = expf(s[2*j][0]   - m0), p01 = expf(s[2*j][1]   - m0);
            float p02 = expf(s[2*j][2]   - m1), p03 = expf(s[2*j][3]   - m1);
            float p10 = expf(s[2*j+1][0] - m0), p11 = expf(s[2*j+1][1] - m0);
            float p12 = expf(s[2*j+1][2] - m1), p13 = expf(s[2*j+1][3] - m1);
            ls0 += p00 + p01 + p10 + p11;
            ls1 += p02 + p03 + p12 + p13;
            pf[j][0] = packh2(p00, p01);
            pf[j][1] = packh2(p02, p03);
            pf[j][2] = packh2(p10, p11);
            pf[j][3] = packh2(p12, p13);
        }
        ls0 += __shfl_xor_sync(0xffffffffu, ls0, 1);
        ls0 += __shfl_xor_sync(0xffffffffu, ls0, 2);
        ls1 += __shfl_xor_sync(0xffffffffu, ls1, 1);
        ls1 += __shfl_xor_sync(0xffffffffu, ls1, 2);
        l0 = l0 * corr0 + ls0;
        l1 = l1 * corr1 + ls1;

        #pragma unroll
        for (int nt = 0; nt < 8; nt++) {
            o[nt][0] *= corr0; o[nt][1] *= corr0;
            o[nt][2] *= corr1; o[nt][3] *= corr1;
        }

        #pragma unroll
        for (int j = 0; j < 4; j++) {
            #pragma unroll
            for (int nt = 0; nt < 8; nt++) {
                uint32_t b0 = Vs2[8*j + tig    ][nt*8 + g];
                uint32_t b1 = Vs2[8*j + tig + 4][nt*8 + g];
                asm volatile(
                    "mma.sync.aligned.m16n8k16.row.col.f32.f16.f16.f32 "
                    "{%0,%1,%2,%3}, {%4,%5,%6,%7}, {%8,%9}, {%0,%1,%2,%3};\n"
                    : "+f"(o[nt][0]), "+f"(o[nt][1]), "+f"(o[nt][2]), "+f"(o[nt][3])
                    : "r"(pf[j][0]), "r"(pf[j][1]), "r"(pf[j][2]), "r"(pf[j][3]),
                      "r"(b0), "r"(b1));
            }
        }
    }

    float inv0 = 1.f / l0, inv1 = 1.f / l1;
    __half* or0 = out + (size_t)(b*SEQ + q0) * DIM + h * HD;
    __half* or1 = out + (size_t)(b*SEQ + q1) * DIM + h * HD;
    #pragma unroll
    for (int nt = 0; nt < 8; nt++) {
        int c = nt*8 + 2*tig;
        *(__half2*)(or0 + c) = __floats2half2_rn(o[nt][0] * inv0, o[nt][1] * inv0);
        *(__half2*)(or1 + c) = __floats2half2_rn(o[nt][2] * inv1, o[nt][3] * inv1);
    }
}

// =================== residual add + LayerNorm (fp32 + fp16 out) ===================
__global__ __launch_bounds__(256) void add_ln_kernel(
    const float* __restrict__ x, const float* __restrict__ a,
    const float* __restrict__ scale, const float* __restrict__ bias,
    float* __restrict__ out, __half* __restrict__ outh, int has_a) {
    int row = blockIdx.x;
    const float* xr = x + (size_t)row * DIM;
    const float* ar = a + (size_t)row * DIM;
    int t = threadIdx.x;
    float v[4];
    float s = 0.f, s2 = 0.f;
    #pragma unroll
    for (int i = 0; i < 4; i++) {
        int d = t + i*256;
        float val = xr[d] + (has_a ? ar[d] : 0.f);
        v[i] = val; s += val; s2 += val*val;
    }
    __shared__ float red[2][8];
    #pragma unroll
    for (int off = 16; off; off >>= 1) {
        s  += __shfl_xor_sync(0xffffffffu, s,  off);
        s2 += __shfl_xor_sync(0xffffffffu, s2, off);
    }
    if ((t & 31) == 0) { red[0][t>>5] = s; red[1][t>>5] = s2; }
    __syncthreads();
    float ts = 0.f, ts2 = 0.f;
    #pragma unroll
    for (int i = 0; i < 8; i++) { ts += red[0][i]; ts2 += red[1][i]; }
    float mean = ts * (1.0f/DIM);
    float var  = ts2 * (1.0f/DIM) - mean*mean;
    float inv  = rsqrtf(var + 1e-5f);
    float*  orow  = out  + (size_t)row * DIM;
    __half* orowh = outh + (size_t)row * DIM;
    #pragma unroll
    for (int i = 0; i < 4; i++) {
        int d = t + i*256;
        float val = (v[i] - mean) * inv * scale[d] + bias[d];
        orow[d]  = val;
        orowh[d] = __float2half(val);
    }
}

// =================== fused-softmax helpers ===================
__global__ void zero_rowsum_kernel(float* __restrict__ rowsum) {
    rowsum[blockIdx.x * 256 + threadIdx.x] = 0.f;
}
__global__ __launch_bounds__(256) void normalize_kernel(float* __restrict__ out,
                                                        const float* __restrict__ rowsum) {
    int row = blockIdx.x;
    float inv = 1.f / rowsum[row];
    float4* r = (float4*)(out + (size_t)row * VOCAB);
    for (int i = threadIdx.x; i < VOCAB/4; i += 256) {
        float4 v = r[i];
        v.x *= inv; v.y *= inv; v.z *= inv; v.w *= inv;
        r[i] = v;
    }
}

// =================== launch ===================
extern "C" void kernel_launch(void* const* d_in, const int* in_sizes, int n_in,
                              void* d_out, int out_size) {
    const int*   X      = (const int*)  d_in[0];
    const float* tok    = (const float*)d_in[1];
    const float* pos    = (const float*)d_in[2];
    const float* qkv_w  = (const float*)d_in[3];
    const float* qkv_b  = (const float*)d_in[4];
    const float* out_w  = (const float*)d_in[5];
    const float* out_b  = (const float*)d_in[6];
    const float* ln1_s  = (const float*)d_in[7];
    const float* ln1_b  = (const float*)d_in[8];
    const float* ln2_s  = (const float*)d_in[9];
    const float* ln2_b  = (const float*)d_in[10];
    const float* ff1_w  = (const float*)d_in[11];
    const float* ff1_b  = (const float*)d_in[12];
    const float* ff2_w  = (const float*)d_in[13];
    const float* ff2_b  = (const float*)d_in[14];
    const float* lnf_s  = (const float*)d_in[15];
    const float* lnf_b  = (const float*)d_in[16];
    const float* head_w = (const float*)d_in[17];
    const float* head_b = (const float*)d_in[18];
    float* outp = (float*)d_out;

    float *x, *tmp, *rowsum;
    __half *xh, *qkvh, *aoh, *ffh;
    uint32_t *qkvwh, *outwh, *ff1wh, *ff2wh, *headwh;
    cudaGetSymbolAddress((void**)&x,      g_x);
    cudaGetSymbolAddress((void**)&xh,     g_xh);
    cudaGetSymbolAddress((void**)&qkvh,   g_qkvh);
    cudaGetSymbolAddress((void**)&aoh,    g_aoh);
    cudaGetSymbolAddress((void**)&ffh,    g_ffh);
    cudaGetSymbolAddress((void**)&tmp,    g_t);
    cudaGetSymbolAddress((void**)&rowsum, g_rowsum);
    cudaGetSymbolAddress((void**)&qkvwh,  g_qkvwh);
    cudaGetSymbolAddress((void**)&outwh,  g_outwh);
    cudaGetSymbolAddress((void**)&ff1wh,  g_ff1wh);
    cudaGetSymbolAddress((void**)&ff2wh,  g_ff2wh);
    cudaGetSymbolAddress((void**)&headwh, g_headwh);

    // one-time weight conversions (per launch), vectorized: (K/2)*(N/4) threads
    convert_w<<<(DIM/2)*(3*DIM/4)/256, 256>>>(qkv_w,  qkvwh,  3*DIM);
    convert_w<<<(DIM/2)*(DIM/4)/256,   256>>>(out_w,  outwh,  DIM);
    convert_w<<<(DIM/2)*(FFD/4)/256,   256>>>(ff1_w,  ff1wh,  FFD);
    convert_w<<<(FFD/2)*(DIM/4)/256,   256>>>(ff2_w,  ff2wh,  DIM);
    convert_w<<<(DIM/2)*(VOCAB/4)/256, 256>>>(head_w, headwh, VOCAB);

    embed_kernel<<<ROWS, 256>>>(X, tok, pos, x, xh);

    for (int l = 0; l < LAYERS; l++) {
        gemm_tc<2,4><<<dim3(3*DIM/128, ROWS/128), 256>>>(xh, qkvwh, qkv_b, qkvh, nullptr, 3*DIM, DIM);
        attn_kernel<<<dim3(SEQ/64, NH, BATCH), 128>>>(qkvh, aoh);
        gemm_tc<0,2><<<dim3(DIM/128, ROWS/64), 256>>>(aoh, outwh, out_b, tmp, nullptr, DIM, DIM);
        add_ln_kernel<<<ROWS, 256>>>(x, tmp, ln1_s, ln1_b, x, xh, 1);
        gemm_tc<1,4><<<dim3(FFD/128, ROWS/128), 256>>>(xh, ff1wh, ff1_b, ffh, nullptr, FFD, DIM);
        gemm_tc<0,2><<<dim3(DIM/128, ROWS/64), 256>>>(ffh, ff2wh, ff2_b, tmp, nullptr, DIM, FFD);
        add_ln_kernel<<<ROWS, 256>>>(x, tmp, ln2_s, ln2_b, x, xh, 1);
    }
    add_ln_kernel<<<ROWS, 256>>>(x, x, lnf_s, lnf_b, x, xh, 0);
    zero_rowsum_kernel<<<ROWS/256, 256>>>(rowsum);
    gemm_tc<3,4><<<dim3(VOCAB/128, ROWS/128), 256>>>(xh, headwh, head_b, outp, rowsum, VOCAB, DIM);
    normalize_kernel<<<ROWS, 256>>>(outp, rowsum);
}

// round 15
// speedup vs baseline: 1.0439x; 1.0229x over previous
#include <cuda_runtime.h>
#include <cuda_fp16.h>
#include <math.h>
#include <stdint.h>

#define SEQ    1024
#define DIM    1024
#define NH     16
#define HD     64
#define LAYERS 6
#define BATCH  2
#define ROWS   (BATCH*SEQ)   // 2048
#define FFD    (4*DIM)       // 4096
#define VOCAB  32000

// ---- scratch (device globals: allocation-free) ----
__device__ float    g_x   [ROWS*DIM];
__device__ __half   g_xh  [ROWS*DIM];
__device__ __half   g_qkvh[ROWS*3*DIM];
__device__ __half   g_aoh [ROWS*DIM];
__device__ __half   g_ffh [ROWS*FFD];
__device__ float    g_t   [ROWS*DIM];
__device__ float    g_rowsum[ROWS];
// fp16 weights, interleaved as half2(W[2k][n], W[2k+1][n]) stored per uint32
__device__ uint32_t g_qkvwh[(DIM/2)*3*DIM];
__device__ uint32_t g_outwh[(DIM/2)*DIM];
__device__ uint32_t g_ff1wh[(DIM/2)*FFD];
__device__ uint32_t g_ff2wh[(FFD/2)*DIM];
__device__ uint32_t g_headwh[(size_t)(DIM/2)*VOCAB];

__device__ __forceinline__ uint32_t packh2(float a, float b) {
    __half2 h = __floats2half2_rn(a, b);
    return *(uint32_t*)&h;
}

// =================== weight conversion (fp32 -> interleaved fp16, vectorized) ===================
__global__ void convert_w(const float* __restrict__ W, uint32_t* __restrict__ Wh, int N) {
    int idx = blockIdx.x * 256 + threadIdx.x;   // over (K/2)*(N/4)
    int n4  = N >> 2;
    int kk  = idx / n4, n = (idx - kk * n4) << 2;
    float4 a = *(const float4*)(W + (size_t)(2*kk)   * N + n);
    float4 b = *(const float4*)(W + (size_t)(2*kk+1) * N + n);
    uint4 o;
    o.x = packh2(a.x, b.x); o.y = packh2(a.y, b.y);
    o.z = packh2(a.z, b.z); o.w = packh2(a.w, b.w);
    *(uint4*)(Wh + (size_t)kk * N + n) = o;
}

// =================== embedding (fp32 + fp16) ===================
__global__ void embed_kernel(const int* __restrict__ X, const float* __restrict__ tok,
                             const float* __restrict__ pos, float* __restrict__ x,
                             __half* __restrict__ xh) {
    int row = blockIdx.x;
    int s   = row % SEQ;
    int v   = X[row];
    const float* te = tok + (size_t)v * DIM;
    const float* pe = pos + (size_t)s * DIM;
    float*  xr  = x  + (size_t)row * DIM;
    __half* xhr = xh + (size_t)row * DIM;
    for (int d = threadIdx.x; d < DIM; d += blockDim.x) {
        float val = te[d] + pe[d];
        xr[d]  = val;
        xhr[d] = __float2half(val);
    }
}

// =================== fp16 tensor-core GEMM, 4-stage cp.async pipeline (R7-proven) ===================
// EPI 0: fp32 out. EPI 1: GELU -> fp16. EPI 2: bias-only -> fp16.
// EPI 3: exp(logit+bias) -> fp32 + atomic row sums (fused softmax numerator).
__device__ __forceinline__ float gelu_exact(float v) {
    return 0.5f * v * (1.0f + erff(v * 0.70710678118654752f));
}
__device__ __forceinline__ void cp16(uint32_t dst, const void* src) {
    asm volatile("cp.async.cg.shared.global [%0], [%1], 16;\n" :: "r"(dst), "l"(src));
}

template<int EPI, int MT>
__global__ __launch_bounds__(256, MT==2 ? 3 : 2) void gemm_tc(
    const __half* __restrict__ A, const uint32_t* __restrict__ Bh,
    const float* __restrict__ bias, void* __restrict__ Cv,
    float* __restrict__ rowsum, int N, int K) {
    constexpr int BM = MT * 32;
    __shared__ __align__(16) uint32_t As2[4][BM][12];
    __shared__ __align__(16) uint32_t Bs2[4][8][136];

    const int t    = threadIdx.x;
    const int warp = t >> 5, lane = t & 31;
    const int wm   = warp >> 2, wn = warp & 3;      // 2 x 4 warp grid
    const int g    = lane >> 2, tig = lane & 3;
    const int bm   = blockIdx.y * BM;
    const int bn   = blockIdx.x * 128;

    const int arow = t >> 1, achk = t & 1;
    const int brow = t >> 5, bcol = (t & 31) << 2;

    float acc[MT][4][4];
    #pragma unroll
    for (int i = 0; i < MT; i++)
        #pragma unroll
        for (int j = 0; j < 4; j++)
            #pragma unroll
            for (int r = 0; r < 4; r++) acc[i][j][r] = 0.f;

    const int nkt = K >> 4;

    #define ISSUE(kt_) do {                                                          \
        int stg_ = (kt_) & 3;                                                        \
        int k0_  = (kt_) << 4;                                                       \
        if (MT == 4 || t < 128) {                                                    \
            uint32_t d_ = (uint32_t)__cvta_generic_to_shared(&As2[stg_][arow][achk*4]); \
            cp16(d_, A + (size_t)(bm + arow) * K + k0_ + achk*8);                    \
        }                                                                            \
        uint32_t d2_ = (uint32_t)__cvta_generic_to_shared(&Bs2[stg_][brow][bcol]);   \
        cp16(d2_, Bh + (size_t)((k0_ >> 1) + brow) * N + bn + bcol);                 \
        asm volatile("cp.async.commit_group;\n");                                    \
    } while (0)

    ISSUE(0); ISSUE(1); ISSUE(2);

    for (int kt = 0; kt < nkt; kt++) {
        asm volatile("cp.async.wait_group 2;\n");
        __syncthreads();
        if (kt + 3 < nkt) ISSUE(kt + 3);
        else              asm volatile("cp.async.commit_group;\n");

        const int cur = kt & 3;
        uint32_t a[MT][4];
        #pragma unroll
        for (int mt = 0; mt < MT; mt++) {
            int m = wm * (MT * 16) + mt * 16 + g;
            a[mt][0] = As2[cur][m    ][tig];
            a[mt][1] = As2[cur][m + 8][tig];
            a[mt][2] = As2[cur][m    ][tig + 4];
            a[mt][3] = As2[cur][m + 8][tig + 4];
        }
        #pragma unroll
        for (int nt = 0; nt < 4; nt++) {
            int n = wn * 32 + nt * 8 + g;
            uint32_t b0 = Bs2[cur][tig    ][n];
            uint32_t b1 = Bs2[cur][tig + 4][n];
            #pragma unroll
            for (int mt = 0; mt < MT; mt++) {
                asm volatile(
                    "mma.sync.aligned.m16n8k16.row.col.f32.f16.f16.f32 "
                    "{%0,%1,%2,%3}, {%4,%5,%6,%7}, {%8,%9}, {%0,%1,%2,%3};\n"
                    : "+f"(acc[mt][nt][0]), "+f"(acc[mt][nt][1]),
                      "+f"(acc[mt][nt][2]), "+f"(acc[mt][nt][3])
                    : "r"(a[mt][0]), "r"(a[mt][1]), "r"(a[mt][2]), "r"(a[mt][3]),
                      "r"(b0), "r"(b1));
            }
        }
    }
    #undef ISSUE

    // epilogue: c0/c1 at (row g, cols 2tig,2tig+1), c2/c3 at row g+8
    float rs0[MT], rs1[MT];
    if (EPI == 3) {
        #pragma unroll
        for (int mt = 0; mt < MT; mt++) { rs0[mt] = 0.f; rs1[mt] = 0.f; }
    }
    #pragma unroll
    for (int nt = 0; nt < 4; nt++) {
        int n = bn + wn * 32 + nt * 8 + 2 * tig;
        float2 bv = *(const float2*)(bias + n);
        #pragma unroll
        for (int mt = 0; mt < MT; mt++) {
            int r = bm + wm * (MT * 16) + mt * 16 + g;
            float o00 = acc[mt][nt][0] + bv.x, o01 = acc[mt][nt][1] + bv.y;
            float o10 = acc[mt][nt][2] + bv.x, o11 = acc[mt][nt][3] + bv.y;
            if (EPI == 1) {
                o00 = gelu_exact(o00); o01 = gelu_exact(o01);
                o10 = gelu_exact(o10); o11 = gelu_exact(o11);
            }
            if (EPI == 3) {
                o00 = expf(o00); o01 = expf(o01);
                o10 = expf(o10); o11 = expf(o11);
                rs0[mt] += o00 + o01;
                rs1[mt] += o10 + o11;
            }
            if (EPI == 1 || EPI == 2) {
                __half* Ch = (__half*)Cv;
                *(__half2*)(Ch + (size_t)r * N + n)       = __floats2half2_rn(o00, o01);
                *(__half2*)(Ch + (size_t)(r + 8) * N + n) = __floats2half2_rn(o10, o11);
            } else {
                float* Cf = (float*)Cv;
                *(float2*)(Cf + (size_t)r * N + n)       = make_float2(o00, o01);
                *(float2*)(Cf + (size_t)(r + 8) * N + n) = make_float2(o10, o11);
            }
        }
    }
    if (EPI == 3) {
        #pragma unroll
        for (int mt = 0; mt < MT; mt++) {
            float s0 = rs0[mt], s1 = rs1[mt];
            s0 += __shfl_xor_sync(0xffffffffu, s0, 1);
            s0 += __shfl_xor_sync(0xffffffffu, s0, 2);
            s1 += __shfl_xor_sync(0xffffffffu, s1, 1);
            s1 += __shfl_xor_sync(0xffffffffu, s1, 2);
            if (tig == 0) {
                int r = bm + wm * (MT * 16) + mt * 16 + g;
                atomicAdd(&rowsum[r],     s0);
                atomicAdd(&rowsum[r + 8], s1);
            }
        }
    }
}

// =================== tensor-core flash attention (fp16 mma, register-prefetched K/V) ===================
__global__ __launch_bounds__(128) void attn_kernel(const __half* __restrict__ qkvh,
                                                   __half* __restrict__ out) {
    __shared__ __align__(16) __half   Qs[64][72];
    __shared__ __align__(16) __half   Ks[64][72];
    __shared__ __align__(16) uint32_t Vs2[32][68];

    const int qt = blockIdx.x, h = blockIdx.y, b = blockIdx.z;
    const int t  = threadIdx.x;
    const int w  = t >> 5, lane = t & 31;
    const int g  = lane >> 2, tig = lane & 3;
    const int RS = 3*DIM;
    const __half* base = qkvh + (size_t)(b*SEQ) * RS + h * (3*HD);

    #pragma unroll
    for (int i = 0; i < 4; i++) {
        int f = t + i*128;
        int r = f >> 3, c = (f & 7) << 3;
        *(uint4*)&Qs[r][c] = *(const uint4*)(base + (size_t)(qt*64 + r) * RS + c);
    }
    __syncthreads();

    uint32_t qf[4][4];
    {
        const __half* r0 = &Qs[w*16 + g    ][0];
        const __half* r8 = &Qs[w*16 + g + 8][0];
        #pragma unroll
        for (int kc = 0; kc < 4; kc++) {
            qf[kc][0] = *(const uint32_t*)(r0 + kc*16 + 2*tig);
            qf[kc][1] = *(const uint32_t*)(r8 + kc*16 + 2*tig);
            qf[kc][2] = *(const uint32_t*)(r0 + kc*16 + 8 + 2*tig);
            qf[kc][3] = *(const uint32_t*)(r8 + kc*16 + 8 + 2*tig);
        }
    }

    float m0 = -INFINITY, m1 = -INFINITY, l0 = 0.f, l1 = 0.f;
    float o[8][4];
    #pragma unroll
    for (int i = 0; i < 8; i++)
        #pragma unroll
        for (int j = 0; j < 4; j++) o[i][j] = 0.f;

    const int q0 = qt*64 + w*16 + g;
    const int q1 = q0 + 8;

    // per-thread tile-load geometry (fixed across kt)
    const int kr0 = t >> 3,        kc0 = (t & 7) << 3;   // K rows t/8, +16, +32, +48
    const int vrp = t >> 3,        vc0 = (t & 7) << 3;   // V pair rows (i*128 offset)

    // register prefetch buffers for K/V tiles
    uint4 kreg[4], vlo[2], vhi[2];
    #define LDG_KV(kt_) do {                                                        \
        _Pragma("unroll")                                                           \
        for (int i_ = 0; i_ < 4; i_++)                                              \
            kreg[i_] = *(const uint4*)(base + (size_t)((kt_)*64 + kr0 + i_*16) * RS + 64 + kc0); \
        _Pragma("unroll")                                                           \
        for (int i_ = 0; i_ < 2; i_++) {                                            \
            const __half* v0_ = base + (size_t)((kt_)*64 + 2*(vrp + i_*16)) * RS + 128 + vc0; \
            vlo[i_] = *(const uint4*)v0_;                                           \
            vhi[i_] = *(const uint4*)(v0_ + RS);                                    \
        }                                                                           \
    } while (0)

    LDG_KV(0);

    for (int kt = 0; kt <= qt; kt++) {
        __syncthreads();   // previous iteration's compute done reading SMEM
        // store prefetched K tile
        #pragma unroll
        for (int i = 0; i < 4; i++)
            *(uint4*)&Ks[kr0 + i*16][kc0] = kreg[i];
        // pack + store prefetched V tile
        #pragma unroll
        for (int i = 0; i < 2; i++) {
            const ushort* ls = (const ushort*)&vlo[i];
            const ushort* hs = (const ushort*)&vhi[i];
            uint32_t pk[8];
            #pragma unroll
            for (int j = 0; j < 8; j++) pk[j] = (uint32_t)ls[j] | ((uint32_t)hs[j] << 16);
            *(uint4*)&Vs2[vrp + i*16][vc0]     = make_uint4(pk[0], pk[1], pk[2], pk[3]);
            *(uint4*)&Vs2[vrp + i*16][vc0 + 4] = make_uint4(pk[4], pk[5], pk[6], pk[7]);
        }
        __syncthreads();
        if (kt < qt) LDG_KV(kt + 1);   // overlap next tile's loads with compute

        float s[8][4];
        #pragma unroll
        for (int i = 0; i < 8; i++)
            #pragma unroll
            for (int j = 0; j < 4; j++) s[i][j] = 0.f;
        #pragma unroll
        for (int kc = 0; kc < 4; kc++) {
            #pragma unroll
            for (int nt = 0; nt < 8; nt++) {
                uint32_t b0 = *(const uint32_t*)(&Ks[nt*8 + g][kc*16 + 2*tig]);
                uint32_t b1 = *(const uint32_t*)(&Ks[nt*8 + g][kc*16 + 8 + 2*tig]);
                asm volatile(
                    "mma.sync.aligned.m16n8k16.row.col.f32.f16.f16.f32 "
                    "{%0,%1,%2,%3}, {%4,%5,%6,%7}, {%8,%9}, {%0,%1,%2,%3};\n"
                    : "+f"(s[nt][0]), "+f"(s[nt][1]), "+f"(s[nt][2]), "+f"(s[nt][3])
                    : "r"(qf[kc][0]), "r"(qf[kc][1]), "r"(qf[kc][2]), "r"(qf[kc][3]),
                      "r"(b0), "r"(b1));
            }
        }

        float tm0 = -INFINITY, tm1 = -INFINITY;
        #pragma unroll
        for (int nt = 0; nt < 8; nt++) {
            int c0 = kt*64 + nt*8 + 2*tig, c1 = c0 + 1;
            s[nt][0] = (c0 <= q0) ? s[nt][0] * 0.125f : -INFINITY;
            s[nt][1] = (c1 <= q0) ? s[nt][1] * 0.125f : -INFINITY;
            s[nt][2] = (c0 <= q1) ? s[nt][2] * 0.125f : -INFINITY;
            s[nt][3] = (c1 <= q1) ? s[nt][3] * 0.125f : -INFINITY;
            tm0 = fmaxf(tm0, fmaxf(s[nt][0], s[nt][1]));
            tm1 = fmaxf(tm1, fmaxf(s[nt][2], s[nt][3]));
        }
        tm0 = fmaxf(tm0, __shfl_xor_sync(0xffffffffu, tm0, 1));
        tm0 = fmaxf(tm0, __shfl_xor_sync(0xffffffffu, tm0, 2));
        tm1 = fmaxf(tm1, __shfl_xor_sync(0xffffffffu, tm1, 1));
        tm1 = fmaxf(tm1, __shfl_xor_sync(0xffffffffu, tm1, 2));

        float nm0 = fmaxf(m0, tm0), nm1 = fmaxf(m1, tm1);
        float corr0 = expf(m0 - nm0), corr1 = expf(m1 - nm1);
        m0 = nm0; m1 = nm1;

        uint32_t pf[4][4];
        float ls0 = 0.f, ls1 = 0.f;
        #pragma unroll
        for (int j = 0; j < 4; j++) {
            float p00 = expf(s[2*j][0]   - m0), p01 = expf(s[2*j][1]   - m0);
            float p02 = expf(s[2*j][2]   - m1), p03 = expf(s[2*j][3]   - m1);
            float p10 = expf(s[2*j+1][0] - m0), p11 = expf(s[2*j+1][1] - m0);
            float p12 = expf(s[2*j+1][2] - m1), p13 = expf(s[2*j+1][3] - m1);
            ls0 += p00 + p01 + p10 + p11;
            ls1 += p02 + p03 + p12 + p13;
            pf[j][0] = packh2(p00, p01);
            pf[j][1] = packh2(p02, p03);
            pf[j][2] = packh2(p10, p11);
            pf[j][3] = packh2(p12, p13);
        }
        ls0 += __shfl_xor_sync(0xffffffffu, ls0, 1);
        ls0 += __shfl_xor_sync(0xffffffffu, ls0, 2);
        ls1 += __shfl_xor_sync(0xffffffffu, ls1, 1);
        ls1 += __shfl_xor_sync(0xffffffffu, ls1, 2);
        l0 = l0 * corr0 + ls0;
        l1 = l1 * corr1 + ls1;

        #pragma unroll
        for (int nt = 0; nt < 8; nt++) {
            o[nt][0] *= corr0; o[nt][1] *= corr0;
            o[nt][2] *= corr1; o[nt][3] *= corr1;
        }

        #pragma unroll
        for (int j = 0; j < 4; j++) {
            #pragma unroll
            for (int nt = 0; nt < 8; nt++) {
                uint32_t b0 = Vs2[8*j + tig    ][nt*8 + g];
                uint32_t b1 = Vs2[8*j + tig + 4][nt*8 + g];
                asm volatile(
                    "mma.sync.aligned.m16n8k16.row.col.f32.f16.f16.f32 "
                    "{%0,%1,%2,%3}, {%4,%5,%6,%7}, {%8,%9}, {%0,%1,%2,%3};\n"
                    : "+f"(o[nt][0]), "+f"(o[nt][1]), "+f"(o[nt][2]), "+f"(o[nt][3])
                    : "r"(pf[j][0]), "r"(pf[j][1]), "r"(pf[j][2]), "r"(pf[j][3]),
                      "r"(b0), "r"(b1));
            }
        }
    }
    #undef LDG_KV

    float inv0 = 1.f / l0, inv1 = 1.f / l1;
    __half* or0 = out + (size_t)(b*SEQ + q0) * DIM + h * HD;
    __half* or1 = out + (size_t)(b*SEQ + q1) * DIM + h * HD;
    #pragma unroll
    for (int nt = 0; nt < 8; nt++) {
        int c = nt*8 + 2*tig;
        *(__half2*)(or0 + c) = __floats2half2_rn(o[nt][0] * inv0, o[nt][1] * inv0);
        *(__half2*)(or1 + c) = __floats2half2_rn(o[nt][2] * inv1, o[nt][3] * inv1);
    }
}

// =================== residual add + LayerNorm (fp32 + fp16 out) ===================
__global__ __launch_bounds__(256) void add_ln_kernel(
    const float* __restrict__ x, const float* __restrict__ a,
    const float* __restrict__ scale, const float* __restrict__ bias,
    float* __restrict__ out, __half* __restrict__ outh, int has_a) {
    int row = blockIdx.x;
    const float* xr = x + (size_t)row * DIM;
    const float* ar = a + (size_t)row * DIM;
    int t = threadIdx.x;
    float v[4];
    float s = 0.f, s2 = 0.f;
    #pragma unroll
    for (int i = 0; i < 4; i++) {
        int d = t + i*256;
        float val = xr[d] + (has_a ? ar[d] : 0.f);
        v[i] = val; s += val; s2 += val*val;
    }
    __shared__ float red[2][8];
    #pragma unroll
    for (int off = 16; off; off >>= 1) {
        s  += __shfl_xor_sync(0xffffffffu, s,  off);
        s2 += __shfl_xor_sync(0xffffffffu, s2, off);
    }
    if ((t & 31) == 0) { red[0][t>>5] = s; red[1][t>>5] = s2; }
    __syncthreads();
    float ts = 0.f, ts2 = 0.f;
    #pragma unroll
    for (int i = 0; i < 8; i++) { ts += red[0][i]; ts2 += red[1][i]; }
    float mean = ts * (1.0f/DIM);
    float var  = ts2 * (1.0f/DIM) - mean*mean;
    float inv  = rsqrtf(var + 1e-5f);
    float*  orow  = out  + (size_t)row * DIM;
    __half* orowh = outh + (size_t)row * DIM;
    #pragma unroll
    for (int i = 0; i < 4; i++) {
        int d = t + i*256;
        float val = (v[i] - mean) * inv * scale[d] + bias[d];
        orow[d]  = val;
        orowh[d] = __float2half(val);
    }
}

// =================== fused-softmax helpers ===================
__global__ void zero_rowsum_kernel(float* __restrict__ rowsum) {
    rowsum[blockIdx.x * 256 + threadIdx.x] = 0.f;
}
__global__ __launch_bounds__(256) void normalize_kernel(float* __restrict__ out,
                                                        const float* __restrict__ rowsum) {
    int row = blockIdx.x;
    float inv = 1.f / rowsum[row];
    float4* r = (float4*)(out + (size_t)row * VOCAB);
    for (int i = threadIdx.x; i < VOCAB/4; i += 256) {
        float4 v = r[i];
        v.x *= inv; v.y *= inv; v.z *= inv; v.w *= inv;
        r[i] = v;
    }
}

// =================== launch ===================
extern "C" void kernel_launch(void* const* d_in, const int* in_sizes, int n_in,
                              void* d_out, int out_size) {
    const int*   X      = (const int*)  d_in[0];
    const float* tok    = (const float*)d_in[1];
    const float* pos    = (const float*)d_in[2];
    const float* qkv_w  = (const float*)d_in[3];
    const float* qkv_b  = (const float*)d_in[4];
    const float* out_w  = (const float*)d_in[5];
    const float* out_b  = (const float*)d_in[6];
    const float* ln1_s  = (const float*)d_in[7];
    const float* ln1_b  = (const float*)d_in[8];
    const float* ln2_s  = (const float*)d_in[9];
    const float* ln2_b  = (const float*)d_in[10];
    const float* ff1_w  = (const float*)d_in[11];
    const float* ff1_b  = (const float*)d_in[12];
    const float* ff2_w  = (const float*)d_in[13];
    const float* ff2_b  = (const float*)d_in[14];
    const float* lnf_s  = (const float*)d_in[15];
    const float* lnf_b  = (const float*)d_in[16];
    const float* head_w = (const float*)d_in[17];
    const float* head_b = (const float*)d_in[18];
    float* outp = (float*)d_out;

    float *x, *tmp, *rowsum;
    __half *xh, *qkvh, *aoh, *ffh;
    uint32_t *qkvwh, *outwh, *ff1wh, *ff2wh, *headwh;
    cudaGetSymbolAddress((void**)&x,      g_x);
    cudaGetSymbolAddress((void**)&xh,     g_xh);
    cudaGetSymbolAddress((void**)&qkvh,   g_qkvh);
    cudaGetSymbolAddress((void**)&aoh,    g_aoh);
    cudaGetSymbolAddress((void**)&ffh,    g_ffh);
    cudaGetSymbolAddress((void**)&tmp,    g_t);
    cudaGetSymbolAddress((void**)&rowsum, g_rowsum);
    cudaGetSymbolAddress((void**)&qkvwh,  g_qkvwh);
    cudaGetSymbolAddress((void**)&outwh,  g_outwh);
    cudaGetSymbolAddress((void**)&ff1wh,  g_ff1wh);
    cudaGetSymbolAddress((void**)&ff2wh,  g_ff2wh);
    cudaGetSymbolAddress((void**)&headwh, g_headwh);

    // one-time weight conversions (per launch), vectorized: (K/2)*(N/4) threads
    convert_w<<<(DIM/2)*(3*DIM/4)/256, 256>>>(qkv_w,  qkvwh,  3*DIM);
    convert_w<<<(DIM/2)*(DIM/4)/256,   256>>>(out_w,  outwh,  DIM);
    convert_w<<<(DIM/2)*(FFD/4)/256,   256>>>(ff1_w,  ff1wh,  FFD);
    convert_w<<<(FFD/2)*(DIM/4)/256,   256>>>(ff2_w,  ff2wh,  DIM);
    convert_w<<<(DIM/2)*(VOCAB/4)/256, 256>>>(head_w, headwh, VOCAB);

    embed_kernel<<<ROWS, 256>>>(X, tok, pos, x, xh);

    for (int l = 0; l < LAYERS; l++) {
        gemm_tc<2,4><<<dim3(3*DIM/128, ROWS/128), 256>>>(xh, qkvwh, qkv_b, qkvh, nullptr, 3*DIM, DIM);
        attn_kernel<<<dim3(SEQ/64, NH, BATCH), 128>>>(qkvh, aoh);
        gemm_tc<0,2><<<dim3(DIM/128, ROWS/64), 256>>>(aoh, outwh, out_b, tmp, nullptr, DIM, DIM);
        add_ln_kernel<<<ROWS, 256>>>(x, tmp, ln1_s, ln1_b, x, xh, 1);
        gemm_tc<1,4><<<dim3(FFD/128, ROWS/128), 256>>>(xh, ff1wh, ff1_b, ffh, nullptr, FFD, DIM);
        gemm_tc<0,2><<<dim3(DIM/128, ROWS/64), 256>>>(ffh, ff2wh, ff2_b, tmp, nullptr, DIM, FFD);
        add_ln_kernel<<<ROWS, 256>>>(x, tmp, ln2_s, ln2_b, x, xh, 1);
    }
    add_ln_kernel<<<ROWS, 256>>>(x, x, lnf_s, lnf_b, x, xh, 0);
    zero_rowsum_kernel<<<ROWS/256, 256>>>(rowsum);
    gemm_tc<3,4><<<dim3(VOCAB/128, ROWS/128), 256>>>(xh, headwh, head_b, outp, rowsum, VOCAB, DIM);
    normalize_kernel<<<ROWS, 256>>>(outp, rowsum);
}